// round 1
// baseline (speedup 1.0000x reference)
#include <cuda_runtime.h>

// Problem constants
#define BB   4
#define TT   2048
#define CC   1024
#define NH   16
#define HD   64
#define MTOT (BB * TT)        // 8192 rows for all projection GEMMs

// Scratch (device-global: no runtime allocation allowed)
__device__ float g_Q[BB * TT * CC];
__device__ float g_K[BB * TT * CC];
__device__ float g_V[BB * TT * CC];
__device__ float g_Y[BB * TT * CC];

// ---------------------------------------------------------------------------
// SGEMM (NT): C[M,N] = A[M,K] @ B[N,K]^T   (both operands K-contiguous)
// 128x128 tile, BK=16, 256 threads, 8x8 per-thread register tile.
// ---------------------------------------------------------------------------
__global__ __launch_bounds__(256) void sgemm_nt(const float* __restrict__ A,
                                                const float* __restrict__ Bm,
                                                float* __restrict__ Cm,
                                                int M, int N, int K) {
    __shared__ float As[16][132];   // [k][m], 132 pad keeps 16B row alignment
    __shared__ float Bs[16][132];   // [k][n]

    const int bm  = blockIdx.y * 128;
    const int bn  = blockIdx.x * 128;
    const int tid = threadIdx.x;
    const int tx  = tid & 15;       // 0..15  -> N direction
    const int ty  = tid >> 4;       // 0..15  -> M direction

    float acc[8][8];
#pragma unroll
    for (int i = 0; i < 8; i++)
#pragma unroll
        for (int j = 0; j < 8; j++) acc[i][j] = 0.0f;

    for (int k0 = 0; k0 < K; k0 += 16) {
        // Stage A and B tiles (transposed to k-major) — 2 float4 each per thread
#pragma unroll
        for (int i = 0; i < 2; i++) {
            int idx = tid + i * 256;      // 0..511
            int row = idx >> 2;           // 0..127
            int c4  = (idx & 3) * 4;      // 0,4,8,12
            float4 a = *(const float4*)(A + (size_t)(bm + row) * K + k0 + c4);
            As[c4 + 0][row] = a.x; As[c4 + 1][row] = a.y;
            As[c4 + 2][row] = a.z; As[c4 + 3][row] = a.w;
            float4 b = *(const float4*)(Bm + (size_t)(bn + row) * K + k0 + c4);
            Bs[c4 + 0][row] = b.x; Bs[c4 + 1][row] = b.y;
            Bs[c4 + 2][row] = b.z; Bs[c4 + 3][row] = b.w;
        }
        __syncthreads();

#pragma unroll
        for (int kk = 0; kk < 16; kk++) {
            float a[8], b[8];
            *(float4*)&a[0] = *(float4*)&As[kk][ty * 4];
            *(float4*)&a[4] = *(float4*)&As[kk][64 + ty * 4];
            *(float4*)&b[0] = *(float4*)&Bs[kk][tx * 4];
            *(float4*)&b[4] = *(float4*)&Bs[kk][64 + tx * 4];
#pragma unroll
            for (int i = 0; i < 8; i++)
#pragma unroll
                for (int j = 0; j < 8; j++) acc[i][j] += a[i] * b[j];
        }
        __syncthreads();
    }

#pragma unroll
    for (int i = 0; i < 8; i++) {
        int row = bm + ((i < 4) ? (ty * 4 + i) : (64 + ty * 4 + (i - 4)));
        float4 c0 = make_float4(acc[i][0], acc[i][1], acc[i][2], acc[i][3]);
        float4 c1 = make_float4(acc[i][4], acc[i][5], acc[i][6], acc[i][7]);
        *(float4*)(Cm + (size_t)row * N + bn + tx * 4)      = c0;
        *(float4*)(Cm + (size_t)row * N + bn + 64 + tx * 4) = c1;
    }
}

// ---------------------------------------------------------------------------
// Flash attention (causal). One block = one (b, h, 64-row Q tile).
// 256 threads as 16x16: thread owns 4 q-rows (ty) x 4 cols/dims (tx).
// Smem: QsT[d][q], KsT[d][k] (aliased as PsT[k][q] in phase 2), Vs[k][d].
// ---------------------------------------------------------------------------
#define FPAD 68     // 64 + 4 pad, keeps float4 alignment per row

__global__ __launch_bounds__(256) void flash_attn(const float* __restrict__ Q,
                                                  const float* __restrict__ K,
                                                  const float* __restrict__ V,
                                                  float* __restrict__ Y) {
    extern __shared__ float sm[];
    float* QsT = sm;                 // [64][FPAD]  QsT[d][q]
    float* KsT = sm + 64 * FPAD;     // [64][FPAD]  KsT[d][k]  (phase 1)
    float* Vs  = sm + 2 * 64 * FPAD; // [64][FPAD]  Vs[k][d]
    float* PsT = KsT;                // [64][FPAD]  PsT[k][q]  (phase 2, aliases KsT)

    const int qt  = blockIdx.x;      // 0..31
    const int h   = blockIdx.y;      // 0..15
    const int b   = blockIdx.z;      // 0..3
    const int tid = threadIdx.x;
    const int tx  = tid & 15;
    const int ty  = tid >> 4;

    const float* Qb = Q + ((size_t)b * TT + qt * 64) * CC + h * HD;
    const float* Kb = K + (size_t)b * TT * CC + h * HD;
    const float* Vb = V + (size_t)b * TT * CC + h * HD;

    // Load Q tile transposed: 64 rows x 64 dims, 4 float4 per thread
#pragma unroll
    for (int i = 0; i < 4; i++) {
        int idx = tid + i * 256;     // 0..1023
        int row = idx >> 4;          // 0..63
        int d4  = (idx & 15) * 4;
        float4 v = *(const float4*)(Qb + (size_t)row * CC + d4);
        QsT[(d4 + 0) * FPAD + row] = v.x;
        QsT[(d4 + 1) * FPAD + row] = v.y;
        QsT[(d4 + 2) * FPAD + row] = v.z;
        QsT[(d4 + 3) * FPAD + row] = v.w;
    }

    float m_i[4], l_i[4], O[4][4];
#pragma unroll
    for (int i = 0; i < 4; i++) {
        m_i[i] = -1e30f; l_i[i] = 0.0f;
#pragma unroll
        for (int j = 0; j < 4; j++) O[i][j] = 0.0f;
    }

    const float scale = 0.125f;      // 1/sqrt(64)

    for (int kt = 0; kt <= qt; kt++) {
        const float* Kt = Kb + (size_t)kt * 64 * CC;
        const float* Vt = Vb + (size_t)kt * 64 * CC;

        __syncthreads();  // previous iter done reading PsT(=KsT)/Vs; QsT ready (iter 0)
#pragma unroll
        for (int i = 0; i < 4; i++) {
            int idx = tid + i * 256;
            int row = idx >> 4;
            int d4  = (idx & 15) * 4;
            float4 kv = *(const float4*)(Kt + (size_t)row * CC + d4);
            KsT[(d4 + 0) * FPAD + row] = kv.x;
            KsT[(d4 + 1) * FPAD + row] = kv.y;
            KsT[(d4 + 2) * FPAD + row] = kv.z;
            KsT[(d4 + 3) * FPAD + row] = kv.w;
            float4 vv = *(const float4*)(Vt + (size_t)row * CC + d4);
            *(float4*)&Vs[row * FPAD + d4] = vv;
        }
        __syncthreads();

        // S = Q K^T  (4x4 per thread)
        float S[4][4];
#pragma unroll
        for (int i = 0; i < 4; i++)
#pragma unroll
            for (int j = 0; j < 4; j++) S[i][j] = 0.0f;

#pragma unroll 16
        for (int d = 0; d < 64; d++) {
            float a[4], bq[4];
            *(float4*)a  = *(float4*)&QsT[d * FPAD + ty * 4];
            *(float4*)bq = *(float4*)&KsT[d * FPAD + tx * 4];
#pragma unroll
            for (int i = 0; i < 4; i++)
#pragma unroll
                for (int j = 0; j < 4; j++) S[i][j] += a[i] * bq[j];
        }

        // scale + causal mask (only the diagonal tile needs masking)
        const int qbase = qt * 64 + ty * 4;
        const int kbase = kt * 64 + tx * 4;
#pragma unroll
        for (int i = 0; i < 4; i++)
#pragma unroll
            for (int j = 0; j < 4; j++) {
                S[i][j] *= scale;
                if (kt == qt && (kbase + j) > (qbase + i)) S[i][j] = -1e30f;
            }

        // online softmax (row reductions across the 16 tx lanes)
        float alpha[4];
#pragma unroll
        for (int i = 0; i < 4; i++) {
            float rm = fmaxf(fmaxf(S[i][0], S[i][1]), fmaxf(S[i][2], S[i][3]));
#pragma unroll
            for (int off = 8; off >= 1; off >>= 1)
                rm = fmaxf(rm, __shfl_xor_sync(0xffffffffu, rm, off));
            float mnew = fmaxf(m_i[i], rm);
            alpha[i] = __expf(m_i[i] - mnew);
            m_i[i] = mnew;

            float rs = 0.0f;
#pragma unroll
            for (int j = 0; j < 4; j++) {
                S[i][j] = __expf(S[i][j] - mnew);
                rs += S[i][j];
            }
#pragma unroll
            for (int off = 8; off >= 1; off >>= 1)
                rs += __shfl_xor_sync(0xffffffffu, rs, off);
            l_i[i] = l_i[i] * alpha[i] + rs;
#pragma unroll
            for (int j = 0; j < 4; j++) O[i][j] *= alpha[i];
        }

        __syncthreads();  // all threads done reading KsT before P overwrites it
#pragma unroll
        for (int i = 0; i < 4; i++)
#pragma unroll
            for (int j = 0; j < 4; j++)
                PsT[(tx * 4 + j) * FPAD + ty * 4 + i] = S[i][j];
        __syncthreads();

        // O += P V
#pragma unroll 16
        for (int kk = 0; kk < 64; kk++) {
            float p[4], vv[4];
            *(float4*)p  = *(float4*)&PsT[kk * FPAD + ty * 4];
            *(float4*)vv = *(float4*)&Vs[kk * FPAD + tx * 4];
#pragma unroll
            for (int i = 0; i < 4; i++)
#pragma unroll
                for (int j = 0; j < 4; j++) O[i][j] += p[i] * vv[j];
        }
    }

    // normalize + write back (head h columns of Y)
    float* Yb = Y + ((size_t)b * TT + qt * 64) * CC + h * HD;
#pragma unroll
    for (int i = 0; i < 4; i++) {
        float inv = 1.0f / l_i[i];
        float4 o = make_float4(O[i][0] * inv, O[i][1] * inv,
                               O[i][2] * inv, O[i][3] * inv);
        *(float4*)(Yb + (size_t)(ty * 4 + i) * CC + tx * 4) = o;
    }
}

// ---------------------------------------------------------------------------
// Launcher
// ---------------------------------------------------------------------------
extern "C" void kernel_launch(void* const* d_in, const int* in_sizes, int n_in,
                              void* d_out, int out_size) {
    const float* x  = (const float*)d_in[0];
    const float* Wq = (const float*)d_in[1];
    const float* Wk = (const float*)d_in[2];
    const float* Wv = (const float*)d_in[3];
    const float* Wo = (const float*)d_in[4];
    float* out = (float*)d_out;

    float *q, *k, *v, *y;
    cudaGetSymbolAddress((void**)&q, g_Q);
    cudaGetSymbolAddress((void**)&k, g_K);
    cudaGetSymbolAddress((void**)&v, g_V);
    cudaGetSymbolAddress((void**)&y, g_Y);

    const int flash_smem = 3 * 64 * FPAD * (int)sizeof(float);  // 52224 B
    cudaFuncSetAttribute(flash_attn, cudaFuncAttributeMaxDynamicSharedMemorySize,
                         flash_smem);

    dim3 gemm_grid(CC / 128, MTOT / 128);   // (8, 64)

    sgemm_nt<<<gemm_grid, 256>>>(x, Wq, q, MTOT, CC, CC);
    sgemm_nt<<<gemm_grid, 256>>>(x, Wk, k, MTOT, CC, CC);
    sgemm_nt<<<gemm_grid, 256>>>(x, Wv, v, MTOT, CC, CC);

    dim3 attn_grid(TT / 64, NH, BB);        // (32, 16, 4)
    flash_attn<<<attn_grid, 256, flash_smem>>>(q, k, v, y);

    sgemm_nt<<<gemm_grid, 256>>>(y, Wo, out, MTOT, CC, CC);
}